// round 16
// baseline (speedup 1.0000x reference)
#include <cuda_runtime.h>
#include <cuda_bf16.h>
#include <cstdint>

// Problem constants
#define BATCH 8
#define DIM   512
#define SEQ   8192
#define HALF  256

// ---------------------------------------------------------------------------
// Static device scratch
// ---------------------------------------------------------------------------
__device__ float         g_hg   [2ULL * BATCH * DIM * SEQ];     // 268 MB fp32
__device__ __nv_bfloat16 g_xt_hi[(size_t)BATCH * SEQ * DIM];    // [b][l][d]
__device__ __nv_bfloat16 g_xt_lo[(size_t)BATCH * SEQ * DIM];
__device__ __nv_bfloat16 g_w_hi [2 * DIM * DIM];                // [dir*512+e][d]
__device__ __nv_bfloat16 g_w_lo [2 * DIM * DIM];

// ---------------------------------------------------------------------------
// Helpers (plain sm_80-era PTX — compiles at compute_103)
// ---------------------------------------------------------------------------
__device__ __forceinline__ uint32_t smem_u32(const void* p) {
    uint32_t a;
    asm("{ .reg .u64 t; cvta.to.shared.u64 t, %1; cvt.u32.u64 %0, t; }" : "=r"(a) : "l"(p));
    return a;
}
__device__ __forceinline__ void cpasync16(uint32_t dst, const void* src) {
    asm volatile("cp.async.cg.shared.global [%0], [%1], 16;" :: "r"(dst), "l"(src) : "memory");
}
#define CP_COMMIT() asm volatile("cp.async.commit_group;" ::: "memory")

#define LDSM_X4(r0, r1, r2, r3, addr) \
    asm volatile("ldmatrix.sync.aligned.m8n8.x4.shared.b16 {%0,%1,%2,%3}, [%4];" \
                 : "=r"(r0), "=r"(r1), "=r"(r2), "=r"(r3) : "r"(addr))

#define MMA16816(d, a, b0, b1) \
    asm volatile("mma.sync.aligned.m16n8k16.row.col.f32.bf16.bf16.f32 " \
                 "{%0,%1,%2,%3},{%4,%5,%6,%7},{%8,%9},{%0,%1,%2,%3};" \
                 : "+f"((d)[0]), "+f"((d)[1]), "+f"((d)[2]), "+f"((d)[3]) \
                 : "r"((a)[0]), "r"((a)[1]), "r"((a)[2]), "r"((a)[3]), "r"(b0), "r"(b1))

// ---------------------------------------------------------------------------
// Prepass 1: W (both dirs) -> bf16 hi/lo, layout [dir*512+e][d]
// ---------------------------------------------------------------------------
__global__ void wconv_kernel(const float* __restrict__ w_fore, const float* __restrict__ w_back)
{
    int idx = blockIdx.x * 256 + threadIdx.x;
    int row = idx >> 9;
    int col = idx & 511;
    float v = (row < DIM) ? w_fore[(size_t)row * DIM + col]
                          : w_back[(size_t)(row - DIM) * DIM + col];
    __nv_bfloat16 hi = __float2bfloat16(v);
    float r = v - __bfloat162float(hi);
    g_w_hi[idx] = hi;
    g_w_lo[idx] = __float2bfloat16(r);
}

// ---------------------------------------------------------------------------
// Prepass 2: X [b][d][l] fp32 -> Xt [b][l][d] bf16 hi/lo (32x32 transpose)
// ---------------------------------------------------------------------------
__global__ __launch_bounds__(256)
void xconv_kernel(const float* __restrict__ x)
{
    __shared__ float tile[32][33];
    const int l0 = blockIdx.x * 32;
    const int d0 = blockIdx.y * 32;
    const int b  = blockIdx.z;
    const int tx = threadIdx.x & 31;
    const int ty = threadIdx.x >> 5;

#pragma unroll
    for (int j = 0; j < 4; j++)
        tile[ty + 8 * j][tx] = x[((size_t)b * DIM + (d0 + ty + 8 * j)) * SEQ + l0 + tx];
    __syncthreads();
#pragma unroll
    for (int j = 0; j < 4; j++) {
        float v = tile[tx][ty + 8 * j];
        __nv_bfloat16 hi = __float2bfloat16(v);
        float r = v - __bfloat162float(hi);
        size_t o = ((size_t)b * SEQ + (l0 + ty + 8 * j)) * DIM + d0 + tx;
        g_xt_hi[o] = hi;
        g_xt_lo[o] = __float2bfloat16(r);
    }
}

// ---------------------------------------------------------------------------
// bf16 mma.sync GEMM, 3-term split (hi*hi + hi*lo + lo*hi), fp32 acc.
// CTA tile 128x128, BK=64, 8 warps (2x4), warp tile 64x32.
// 3-stage cp.async pipeline, ONE __syncthreads per stage.
// Smem row stride 144 B -> ldmatrix conflict-free.
// ---------------------------------------------------------------------------
#define ROWB      144
#define TILE_B    (128 * ROWB)              // 18432 B
#define OFF_AHI   0
#define OFF_ALO   (TILE_B)
#define OFF_BHI   (2 * TILE_B)
#define OFF_BLO   (3 * TILE_B)
#define STAGE_B   (4 * TILE_B)              // 73728 B
#define GEMM_SMEM (3 * STAGE_B)             // 221184 B (3-stage)

__global__ __launch_bounds__(256, 1)
void gemm_mma_kernel(const float* __restrict__ bias_fore, const float* __restrict__ bias_back)
{
    extern __shared__ __align__(16) char smraw[];
    const uint32_t sbase = smem_u32(smraw);

    const int tid  = threadIdx.x;
    const int lane = tid & 31;
    const int wid  = tid >> 5;
    const int wm   = wid >> 2;          // 0..1
    const int wn   = wid & 3;           // 0..3

    const int mt = blockIdx.x;          // 0..7
    const int nt = blockIdx.y;          // 0..63
    const int b  = blockIdx.z;
    const int m0 = mt * 128;
    const int n0 = nt * 128;

    const __nv_bfloat16* __restrict__ Whi = g_w_hi + (size_t)m0 * DIM;
    const __nv_bfloat16* __restrict__ Wlo = g_w_lo + (size_t)m0 * DIM;
    const __nv_bfloat16* __restrict__ Xhi = g_xt_hi + ((size_t)b * SEQ + n0) * DIM;
    const __nv_bfloat16* __restrict__ Xlo = g_xt_lo + ((size_t)b * SEQ + n0) * DIM;

    auto load_stage = [&](int s) {
        const int k0 = s * 64;
        const uint32_t buf = sbase + (uint32_t)(s % 3) * STAGE_B;
#pragma unroll
        for (int it = 0; it < 4; it++) {
            int u   = tid + 256 * it;           // 0..1023
            int row = u >> 3, c = u & 7;
            uint32_t doff = (uint32_t)row * ROWB + c * 16;
            size_t   goff = (size_t)row * DIM + k0 + c * 8;
            cpasync16(buf + OFF_AHI + doff, Whi + goff);
            cpasync16(buf + OFF_ALO + doff, Wlo + goff);
            cpasync16(buf + OFF_BHI + doff, Xhi + goff);
            cpasync16(buf + OFF_BLO + doff, Xlo + goff);
        }
        CP_COMMIT();
    };

    float acc[4][4][4];
#pragma unroll
    for (int i = 0; i < 4; i++)
#pragma unroll
        for (int j = 0; j < 4; j++)
#pragma unroll
            for (int q = 0; q < 4; q++) acc[i][j][q] = 0.f;

    const uint32_t a_base = (uint32_t)(wm * 64 + (lane & 15)) * ROWB + ((lane >> 4) * 8) * 2;
    const uint32_t b_base = (uint32_t)(wn * 32 + (lane & 7) + ((lane & 16) >> 1)) * ROWB
                          + (uint32_t)(lane & 8) * 2;

    load_stage(0);
    load_stage(1);

    for (int s = 0; s < 8; s++) {
        // Guarantee group s complete: outstanding = {s, s+1} (s<7) -> allow 1 pending.
        if (s < 7) asm volatile("cp.async.wait_group 1;" ::: "memory");
        else       asm volatile("cp.async.wait_group 0;" ::: "memory");
        __syncthreads();
        // Slot (s+2)%3 was last READ at stage s-1; all warps passed that compute
        // before this barrier -> safe to refill now, overlapping compute of s.
        if (s + 2 < 8) load_stage(s + 2);

        const uint32_t buf = sbase + (uint32_t)(s % 3) * STAGE_B;
#pragma unroll
        for (int ks = 0; ks < 4; ks++) {
            const uint32_t kb = ks * 32;
            uint32_t ah[4][4], al[4][4], bh[2][4], bl[2][4];
#pragma unroll
            for (int m4 = 0; m4 < 4; m4++) {
                uint32_t ad = buf + a_base + (uint32_t)m4 * 16 * ROWB + kb;
                LDSM_X4(ah[m4][0], ah[m4][1], ah[m4][2], ah[m4][3], ad + OFF_AHI);
                LDSM_X4(al[m4][0], al[m4][1], al[m4][2], al[m4][3], ad + OFF_ALO);
            }
#pragma unroll
            for (int np = 0; np < 2; np++) {
                uint32_t bd = buf + b_base + (uint32_t)np * 16 * ROWB + kb;
                LDSM_X4(bh[np][0], bh[np][1], bh[np][2], bh[np][3], bd + OFF_BHI);
                LDSM_X4(bl[np][0], bl[np][1], bl[np][2], bl[np][3], bd + OFF_BLO);
            }
#pragma unroll
            for (int m4 = 0; m4 < 4; m4++)
#pragma unroll
                for (int n4 = 0; n4 < 4; n4++) {
                    const int np = n4 >> 1, h = (n4 & 1) * 2;
                    MMA16816(acc[m4][n4], ah[m4], bh[np][h], bh[np][h + 1]);   // hi*hi
                    MMA16816(acc[m4][n4], ah[m4], bl[np][h], bl[np][h + 1]);   // hi*lo
                    MMA16816(acc[m4][n4], al[m4], bh[np][h], bh[np][h + 1]);   // lo*hi
                }
        }
    }

    // Epilogue
    const int dirM = (m0 >= DIM) ? 1 : 0;
    const float* __restrict__ bias = dirM ? bias_back : bias_fore;
    const int gid = lane >> 2;
    const int qp  = (lane & 3) * 2;

#pragma unroll
    for (int m4 = 0; m4 < 4; m4++) {
#pragma unroll
        for (int hh = 0; hh < 2; hh++) {
            int m = m0 + wm * 64 + m4 * 16 + gid + hh * 8;
            int e = m & (DIM - 1);
            float bi = bias[e];
            float* __restrict__ C = g_hg + (((size_t)dirM * BATCH + b) * DIM + e) * SEQ
                                  + n0 + wn * 32 + qp;
#pragma unroll
            for (int n4 = 0; n4 < 4; n4++) {
                float2 v = make_float2(acc[m4][n4][hh * 2] + bi, acc[m4][n4][hh * 2 + 1] + bi);
                *reinterpret_cast<float2*>(C + n4 * 8) = v;
            }
        }
    }
}

// ---------------------------------------------------------------------------
// minGRU scan — register-resident segment scan, one barrier.
// h_t = a_t*h_{t-1} + b_t, a=sigmoid(-g), b=sigmoid(g)*g(h), h0=0.
// Thread owns 32 CONTIGUOUS scan positions p in [32*tid, 32*tid+32).
// dir==1: scan position p maps to gmem index l = SEQ-1-p; float4 chunks are
// loaded at i4 = SEQ/4-1-8*tid-q with in-register element reversal.
// Block combine: 5-step warp shuffle scan + 8 warp totals via smem.
// ---------------------------------------------------------------------------
__global__ __launch_bounds__(256, 2)
void scan_kernel(const float* __restrict__ hg, float* __restrict__ out)
{
    __shared__ float swA[8], swB[8];

    const int id   = blockIdx.x;            // 0..4095
    const int dir  = id >> 11;
    const int rem  = id & 2047;
    const int b    = rem >> 8;
    const int ch   = rem & 255;
    const int tid  = threadIdx.x;
    const int lane = tid & 31;
    const int wid  = tid >> 5;

    const float4* __restrict__ h4 =
        (const float4*)(hg + (((size_t)dir * BATCH + b) * DIM + ch) * SEQ);
    const float4* __restrict__ g4 =
        (const float4*)(hg + (((size_t)dir * BATCH + b) * DIM + ch + HALF) * SEQ);

    float av[32], bv[32];
    float A = 1.f, Bc = 0.f;

#pragma unroll
    for (int q = 0; q < 8; q++) {
        int i4 = dir ? (SEQ / 4 - 1 - 8 * tid - q) : (8 * tid + q);
        float4 hv = h4[i4];
        float4 gv = g4[i4];
        float hh[4] = { hv.x, hv.y, hv.z, hv.w };
        float gg[4] = { gv.x, gv.y, gv.z, gv.w };
#pragma unroll
        for (int r = 0; r < 4; r++) {
            int m = dir ? (3 - r) : r;       // memory elem -> scan order
            float h = hh[m], g = gg[m];
            float s  = 1.f / (1.f + __expf(-g));
            float a  = 1.f / (1.f + __expf(g));
            float gh = (h >= 0.f) ? (1.f + h) : __expf(h);
            int j = 4 * q + r;
            av[j] = a;
            bv[j] = s * gh;
            A  = a * A;
            Bc = fmaf(a, Bc, bv[j]);
        }
    }

    // Warp inclusive scan of affine pairs: compose(left, own) = (A*la, A*lb + B).
    float ca = A, cb = Bc;
#pragma unroll
    for (int off = 1; off < 32; off <<= 1) {
        float pa = __shfl_up_sync(0xffffffffu, ca, off);
        float pb = __shfl_up_sync(0xffffffffu, cb, off);
        float na = ca * pa;
        float nb = fmaf(ca, pb, cb);
        if (lane >= off) { ca = na; cb = nb; }
    }
    if (lane == 31) { swA[wid] = ca; swB[wid] = cb; }

    // Exclusive-within-warp pair (identity at lane 0).
    float Ea = __shfl_up_sync(0xffffffffu, ca, 1);
    float Eb = __shfl_up_sync(0xffffffffu, cb, 1);
    if (lane == 0) { Ea = 1.f; Eb = 0.f; }

    __syncthreads();

    // Exclusive prefix over warps (serial over <=7 totals).
    float Pa = 1.f, Pb = 0.f;
    for (int w = 0; w < wid; w++) {
        float wa = swA[w], wb = swB[w];
        Pb = fmaf(wa, Pb, wb);
        Pa = wa * Pa;
    }
    (void)Pa;

    // h at this thread's segment start (h0 = 0): B of compose(P, E).
    float h = fmaf(Ea, Pb, Eb);

    float4* __restrict__ o4 =
        (float4*)(out + (((size_t)b * DIM) + dir * HALF + ch) * SEQ);
#pragma unroll
    for (int q = 0; q < 8; q++) {
        float o[4];
#pragma unroll
        for (int r = 0; r < 4; r++) {
            int j = 4 * q + r;
            h = fmaf(av[j], h, bv[j]);
            o[r] = h;
        }
        int i4 = dir ? (SEQ / 4 - 1 - 8 * tid - q) : (8 * tid + q);
        float4 ov = dir ? make_float4(o[3], o[2], o[1], o[0])
                        : make_float4(o[0], o[1], o[2], o[3]);
        o4[i4] = ov;
    }
}

// ---------------------------------------------------------------------------
// Launch — stateless, graph-capturable
// ---------------------------------------------------------------------------
extern "C" void kernel_launch(void* const* d_in, const int* in_sizes, int n_in,
                              void* d_out, int out_size)
{
    const float* x      = (const float*)d_in[0];
    const float* w_fore = (const float*)d_in[1];
    const float* b_fore = (const float*)d_in[2];
    const float* w_back = (const float*)d_in[3];
    const float* b_back = (const float*)d_in[4];
    float* out = (float*)d_out;

    float* hg = nullptr;
    cudaGetSymbolAddress((void**)&hg, g_hg);

    // Prepass: bf16 hi/lo conversion (X transposed to [b][l][d]).
    wconv_kernel<<<2 * DIM * DIM / 256, 256>>>(w_fore, w_back);
    xconv_kernel<<<dim3(SEQ / 32, DIM / 32, BATCH), 256>>>(x);

    // Tensor-core GEMM (mma.sync bf16 3-term, 3-stage pipeline).
    cudaFuncSetAttribute(gemm_mma_kernel, cudaFuncAttributeMaxDynamicSharedMemorySize, GEMM_SMEM);
    gemm_mma_kernel<<<dim3(8, 64, BATCH), 256, GEMM_SMEM>>>(b_fore, b_back);

    // Scan (no dynamic smem needed anymore).
    scan_kernel<<<2 * BATCH * HALF, 256>>>(hg, out);
}

// round 17
// speedup vs baseline: 1.5950x; 1.5950x over previous
#include <cuda_runtime.h>
#include <cuda_bf16.h>
#include <cuda_fp16.h>
#include <cstdint>

// Problem constants
#define BATCH 8
#define DIM   512
#define SEQ   8192
#define HALF  256

// ---------------------------------------------------------------------------
// Static device scratch
// ---------------------------------------------------------------------------
__device__ __half        g_hg   [2ULL * BATCH * DIM * SEQ];     // 134 MB fp16
__device__ __nv_bfloat16 g_xt_hi[(size_t)BATCH * SEQ * DIM];    // [b][l][d]
__device__ __nv_bfloat16 g_xt_lo[(size_t)BATCH * SEQ * DIM];
__device__ __nv_bfloat16 g_w_hi [2 * DIM * DIM];                // [dir*512+e][d]
__device__ __nv_bfloat16 g_w_lo [2 * DIM * DIM];

// ---------------------------------------------------------------------------
// Helpers (plain sm_80-era PTX — compiles at compute_103)
// ---------------------------------------------------------------------------
__device__ __forceinline__ uint32_t smem_u32(const void* p) {
    uint32_t a;
    asm("{ .reg .u64 t; cvta.to.shared.u64 t, %1; cvt.u32.u64 %0, t; }" : "=r"(a) : "l"(p));
    return a;
}
__device__ __forceinline__ void cpasync16(uint32_t dst, const void* src) {
    asm volatile("cp.async.cg.shared.global [%0], [%1], 16;" :: "r"(dst), "l"(src) : "memory");
}
#define CP_COMMIT() asm volatile("cp.async.commit_group;" ::: "memory")

#define LDSM_X4(r0, r1, r2, r3, addr) \
    asm volatile("ldmatrix.sync.aligned.m8n8.x4.shared.b16 {%0,%1,%2,%3}, [%4];" \
                 : "=r"(r0), "=r"(r1), "=r"(r2), "=r"(r3) : "r"(addr))

#define MMA16816(d, a, b0, b1) \
    asm volatile("mma.sync.aligned.m16n8k16.row.col.f32.bf16.bf16.f32 " \
                 "{%0,%1,%2,%3},{%4,%5,%6,%7},{%8,%9},{%0,%1,%2,%3};" \
                 : "+f"((d)[0]), "+f"((d)[1]), "+f"((d)[2]), "+f"((d)[3]) \
                 : "r"((a)[0]), "r"((a)[1]), "r"((a)[2]), "r"((a)[3]), "r"(b0), "r"(b1))

// ---------------------------------------------------------------------------
// Prepass 1: W (both dirs) -> bf16 hi/lo, layout [dir*512+e][d]
// ---------------------------------------------------------------------------
__global__ void wconv_kernel(const float* __restrict__ w_fore, const float* __restrict__ w_back)
{
    int idx = blockIdx.x * 256 + threadIdx.x;
    int row = idx >> 9;
    int col = idx & 511;
    float v = (row < DIM) ? w_fore[(size_t)row * DIM + col]
                          : w_back[(size_t)(row - DIM) * DIM + col];
    __nv_bfloat16 hi = __float2bfloat16(v);
    float r = v - __bfloat162float(hi);
    g_w_hi[idx] = hi;
    g_w_lo[idx] = __float2bfloat16(r);
}

// ---------------------------------------------------------------------------
// Prepass 2: X [b][d][l] fp32 -> Xt [b][l][d] bf16 hi/lo (32x32 transpose)
// ---------------------------------------------------------------------------
__global__ __launch_bounds__(256)
void xconv_kernel(const float* __restrict__ x)
{
    __shared__ float tile[32][33];
    const int l0 = blockIdx.x * 32;
    const int d0 = blockIdx.y * 32;
    const int b  = blockIdx.z;
    const int tx = threadIdx.x & 31;
    const int ty = threadIdx.x >> 5;

#pragma unroll
    for (int j = 0; j < 4; j++)
        tile[ty + 8 * j][tx] = x[((size_t)b * DIM + (d0 + ty + 8 * j)) * SEQ + l0 + tx];
    __syncthreads();
#pragma unroll
    for (int j = 0; j < 4; j++) {
        float v = tile[tx][ty + 8 * j];
        __nv_bfloat16 hi = __float2bfloat16(v);
        float r = v - __bfloat162float(hi);
        size_t o = ((size_t)b * SEQ + (l0 + ty + 8 * j)) * DIM + d0 + tx;
        g_xt_hi[o] = hi;
        g_xt_lo[o] = __float2bfloat16(r);
    }
}

// ---------------------------------------------------------------------------
// bf16 mma.sync GEMM, 3-term split (hi*hi + hi*lo + lo*hi), fp32 acc.
// EXACT R15 schedule (measured ~540us): 2-stage cp.async, issue s+1 before
// waiting on s, two barriers per stage.  Epilogue now stores fp16.
// CTA tile 128x128, BK=64, 8 warps (2x4), warp tile 64x32.
// Smem row stride 144 B -> ldmatrix conflict-free.
// ---------------------------------------------------------------------------
#define ROWB      144
#define TILE_B    (128 * ROWB)              // 18432 B
#define OFF_AHI   0
#define OFF_ALO   (TILE_B)
#define OFF_BHI   (2 * TILE_B)
#define OFF_BLO   (3 * TILE_B)
#define STAGE_B   (4 * TILE_B)              // 73728 B
#define GEMM_SMEM (2 * STAGE_B)             // 147456 B (2-stage)

__global__ __launch_bounds__(256, 1)
void gemm_mma_kernel(const float* __restrict__ bias_fore, const float* __restrict__ bias_back)
{
    extern __shared__ __align__(16) char smraw[];
    const uint32_t sbase = smem_u32(smraw);

    const int tid  = threadIdx.x;
    const int lane = tid & 31;
    const int wid  = tid >> 5;
    const int wm   = wid >> 2;          // 0..1
    const int wn   = wid & 3;           // 0..3

    const int mt = blockIdx.x;          // 0..7
    const int nt = blockIdx.y;          // 0..63
    const int b  = blockIdx.z;
    const int m0 = mt * 128;
    const int n0 = nt * 128;

    const __nv_bfloat16* __restrict__ Whi = g_w_hi + (size_t)m0 * DIM;
    const __nv_bfloat16* __restrict__ Wlo = g_w_lo + (size_t)m0 * DIM;
    const __nv_bfloat16* __restrict__ Xhi = g_xt_hi + ((size_t)b * SEQ + n0) * DIM;
    const __nv_bfloat16* __restrict__ Xlo = g_xt_lo + ((size_t)b * SEQ + n0) * DIM;

    auto load_stage = [&](int s) {
        const int k0 = s * 64;
        const uint32_t buf = sbase + (uint32_t)(s & 1) * STAGE_B;
#pragma unroll
        for (int it = 0; it < 4; it++) {
            int u   = tid + 256 * it;           // 0..1023
            int row = u >> 3, c = u & 7;
            uint32_t doff = (uint32_t)row * ROWB + c * 16;
            size_t   goff = (size_t)row * DIM + k0 + c * 8;
            cpasync16(buf + OFF_AHI + doff, Whi + goff);
            cpasync16(buf + OFF_ALO + doff, Wlo + goff);
            cpasync16(buf + OFF_BHI + doff, Xhi + goff);
            cpasync16(buf + OFF_BLO + doff, Xlo + goff);
        }
        CP_COMMIT();
    };

    float acc[4][4][4];
#pragma unroll
    for (int i = 0; i < 4; i++)
#pragma unroll
        for (int j = 0; j < 4; j++)
#pragma unroll
            for (int q = 0; q < 4; q++) acc[i][j][q] = 0.f;

    const uint32_t a_base = (uint32_t)(wm * 64 + (lane & 15)) * ROWB + ((lane >> 4) * 8) * 2;
    const uint32_t b_base = (uint32_t)(wn * 32 + (lane & 7) + ((lane & 16) >> 1)) * ROWB
                          + (uint32_t)(lane & 8) * 2;

    load_stage(0);

    for (int s = 0; s < 8; s++) {
        if (s < 7) {
            load_stage(s + 1);
            asm volatile("cp.async.wait_group 1;" ::: "memory");
        } else {
            asm volatile("cp.async.wait_group 0;" ::: "memory");
        }
        __syncthreads();

        const uint32_t buf = sbase + (uint32_t)(s & 1) * STAGE_B;
#pragma unroll
        for (int ks = 0; ks < 4; ks++) {
            const uint32_t kb = ks * 32;
            uint32_t ah[4][4], al[4][4], bh[2][4], bl[2][4];
#pragma unroll
            for (int m4 = 0; m4 < 4; m4++) {
                uint32_t ad = buf + a_base + (uint32_t)m4 * 16 * ROWB + kb;
                LDSM_X4(ah[m4][0], ah[m4][1], ah[m4][2], ah[m4][3], ad + OFF_AHI);
                LDSM_X4(al[m4][0], al[m4][1], al[m4][2], al[m4][3], ad + OFF_ALO);
            }
#pragma unroll
            for (int np = 0; np < 2; np++) {
                uint32_t bd = buf + b_base + (uint32_t)np * 16 * ROWB + kb;
                LDSM_X4(bh[np][0], bh[np][1], bh[np][2], bh[np][3], bd + OFF_BHI);
                LDSM_X4(bl[np][0], bl[np][1], bl[np][2], bl[np][3], bd + OFF_BLO);
            }
#pragma unroll
            for (int m4 = 0; m4 < 4; m4++)
#pragma unroll
                for (int n4 = 0; n4 < 4; n4++) {
                    const int np = n4 >> 1, h = (n4 & 1) * 2;
                    MMA16816(acc[m4][n4], ah[m4], bh[np][h], bh[np][h + 1]);   // hi*hi
                    MMA16816(acc[m4][n4], ah[m4], bl[np][h], bl[np][h + 1]);   // hi*lo
                    MMA16816(acc[m4][n4], al[m4], bh[np][h], bh[np][h + 1]);   // lo*hi
                }
        }
        __syncthreads();
    }

    // Epilogue -> fp16 hg
    const int dirM = (m0 >= DIM) ? 1 : 0;
    const float* __restrict__ bias = dirM ? bias_back : bias_fore;
    const int gid = lane >> 2;
    const int qp  = (lane & 3) * 2;

#pragma unroll
    for (int m4 = 0; m4 < 4; m4++) {
#pragma unroll
        for (int hh = 0; hh < 2; hh++) {
            int m = m0 + wm * 64 + m4 * 16 + gid + hh * 8;
            int e = m & (DIM - 1);
            float bi = bias[e];
            __half* __restrict__ C = g_hg + (((size_t)dirM * BATCH + b) * DIM + e) * SEQ
                                   + n0 + wn * 32 + qp;
#pragma unroll
            for (int n4 = 0; n4 < 4; n4++) {
                __half2 v = __floats2half2_rn(acc[m4][n4][hh * 2] + bi,
                                              acc[m4][n4][hh * 2 + 1] + bi);
                *reinterpret_cast<__half2*>(C + n4 * 8) = v;
            }
        }
    }
}

// ---------------------------------------------------------------------------
// minGRU scan — register-resident segment scan, one barrier (R16, fp16 in).
// h_t = a_t*h_{t-1} + b_t, a=sigmoid(-g), b=sigmoid(g)*g(h), h0=0.
// Thread owns 32 contiguous scan positions; fp16 hg read as uint4 (8 halves).
// dir==1: scan position p maps to gmem l = SEQ-1-p (reversed chunks).
// ---------------------------------------------------------------------------
__global__ __launch_bounds__(256, 2)
void scan_kernel(const __half* __restrict__ hg, float* __restrict__ out)
{
    __shared__ float swA[8], swB[8];

    const int id   = blockIdx.x;            // 0..4095
    const int dir  = id >> 11;
    const int rem  = id & 2047;
    const int b    = rem >> 8;
    const int ch   = rem & 255;
    const int tid  = threadIdx.x;
    const int lane = tid & 31;
    const int wid  = tid >> 5;

    const uint4* __restrict__ h8 =
        (const uint4*)(hg + (((size_t)dir * BATCH + b) * DIM + ch) * SEQ);
    const uint4* __restrict__ g8 =
        (const uint4*)(hg + (((size_t)dir * BATCH + b) * DIM + ch + HALF) * SEQ);

    float av[32], bv[32];
    float A = 1.f, Bc = 0.f;

#pragma unroll
    for (int q = 0; q < 4; q++) {                       // 4 chunks of 8 halves
        int i8 = dir ? (SEQ / 8 - 1 - 4 * tid - q) : (4 * tid + q);
        uint4 hv = h8[i8];
        uint4 gv = g8[i8];
        const __half2* hp = reinterpret_cast<const __half2*>(&hv);
        const __half2* gp = reinterpret_cast<const __half2*>(&gv);
        float hh[8], gg[8];
#pragma unroll
        for (int p2 = 0; p2 < 4; p2++) {
            float2 hf = __half22float2(hp[p2]);
            float2 gf = __half22float2(gp[p2]);
            hh[2 * p2] = hf.x; hh[2 * p2 + 1] = hf.y;
            gg[2 * p2] = gf.x; gg[2 * p2 + 1] = gf.y;
        }
#pragma unroll
        for (int r = 0; r < 8; r++) {
            int m = dir ? (7 - r) : r;                  // memory elem -> scan order
            float h = hh[m], g = gg[m];
            float s  = 1.f / (1.f + __expf(-g));
            float a  = 1.f / (1.f + __expf(g));
            float gh = (h >= 0.f) ? (1.f + h) : __expf(h);
            int j = 8 * q + r;
            av[j] = a;
            bv[j] = s * gh;
            A  = a * A;
            Bc = fmaf(a, Bc, bv[j]);
        }
    }

    // Warp inclusive scan of affine pairs: compose(left, own) = (A*la, A*lb + B).
    float ca = A, cb = Bc;
#pragma unroll
    for (int off = 1; off < 32; off <<= 1) {
        float pa = __shfl_up_sync(0xffffffffu, ca, off);
        float pb = __shfl_up_sync(0xffffffffu, cb, off);
        float na = ca * pa;
        float nb = fmaf(ca, pb, cb);
        if (lane >= off) { ca = na; cb = nb; }
    }
    if (lane == 31) { swA[wid] = ca; swB[wid] = cb; }

    // Exclusive-within-warp pair (identity at lane 0).
    float Ea = __shfl_up_sync(0xffffffffu, ca, 1);
    float Eb = __shfl_up_sync(0xffffffffu, cb, 1);
    if (lane == 0) { Ea = 1.f; Eb = 0.f; }

    __syncthreads();

    // Exclusive prefix over warps (serial over <=7 totals).
    float Pb = 0.f;
    for (int w = 0; w < wid; w++) {
        Pb = fmaf(swA[w], Pb, swB[w]);
    }

    // h at this thread's segment start (h0 = 0): B of compose(P, E).
    float h = fmaf(Ea, Pb, Eb);

    float4* __restrict__ o4 =
        (float4*)(out + (((size_t)b * DIM) + dir * HALF + ch) * SEQ);
#pragma unroll
    for (int q = 0; q < 4; q++) {
        float o[8];
#pragma unroll
        for (int r = 0; r < 8; r++) {
            int j = 8 * q + r;
            h = fmaf(av[j], h, bv[j]);
            o[r] = h;
        }
        if (!dir) {
            int i4 = 8 * tid + 2 * q;
            o4[i4]     = make_float4(o[0], o[1], o[2], o[3]);
            o4[i4 + 1] = make_float4(o[4], o[5], o[6], o[7]);
        } else {
            int i4 = SEQ / 4 - 8 * tid - 2 * q - 2;     // lowest-l float4 of chunk
            o4[i4]     = make_float4(o[7], o[6], o[5], o[4]);
            o4[i4 + 1] = make_float4(o[3], o[2], o[1], o[0]);
        }
    }
}

// ---------------------------------------------------------------------------
// Launch — stateless, graph-capturable
// ---------------------------------------------------------------------------
extern "C" void kernel_launch(void* const* d_in, const int* in_sizes, int n_in,
                              void* d_out, int out_size)
{
    const float* x      = (const float*)d_in[0];
    const float* w_fore = (const float*)d_in[1];
    const float* b_fore = (const float*)d_in[2];
    const float* w_back = (const float*)d_in[3];
    const float* b_back = (const float*)d_in[4];
    float* out = (float*)d_out;

    __half* hg = nullptr;
    cudaGetSymbolAddress((void**)&hg, g_hg);

    // Prepass: bf16 hi/lo conversion (X transposed to [b][l][d]).
    wconv_kernel<<<2 * DIM * DIM / 256, 256>>>(w_fore, w_back);
    xconv_kernel<<<dim3(SEQ / 32, DIM / 32, BATCH), 256>>>(x);

    // Tensor-core GEMM (mma.sync bf16 3-term, 2-stage R15 schedule).
    cudaFuncSetAttribute(gemm_mma_kernel, cudaFuncAttributeMaxDynamicSharedMemorySize, GEMM_SMEM);
    gemm_mma_kernel<<<dim3(8, 64, BATCH), 256, GEMM_SMEM>>>(b_fore, b_back);

    // Scan.
    scan_kernel<<<2 * BATCH * HALF, 256>>>(hg, out);
}